// round 14
// baseline (speedup 1.0000x reference)
#include <cuda_runtime.h>
#include <cuda_bf16.h>
#include <cstdint>

#define D_MODEL 1024
#define N_HEAD  16
#define D_HEAD  64
#define BATCH   4
#define SEQ     1024
#define BL      (BATCH*SEQ)     // 4096

// ---------------- bf16 hi/lo pools (static device globals) ----------------
constexpr size_t SZA   = (size_t)BL * D_MODEL;
constexpr size_t SZW   = (size_t)D_MODEL * D_MODEL;
constexpr size_t SZWKV = (size_t)D_MODEL * 128;
constexpr size_t SZWP  = (size_t)2 * D_MODEL * D_MODEL;
constexpr size_t SZKV  = (size_t)BL * 128;
constexpr size_t SZCAT = (size_t)BL * 2 * D_MODEL;

constexpr size_t O_QX   = 0;
constexpr size_t O_QS   = O_QX + SZA;
constexpr size_t O_KVXI = O_QS + SZA;
constexpr size_t O_KVSI = O_KVXI + SZA;
constexpr size_t O_WQX1 = O_KVSI + SZA;
constexpr size_t O_WQS1 = O_WQX1 + SZW;
constexpr size_t O_WQX2 = O_WQS1 + SZW;
constexpr size_t O_WQS2 = O_WQX2 + SZW;
constexpr size_t O_WKVX = O_WQS2 + SZW;
constexpr size_t O_WKVS = O_WKVX + SZWKV;
constexpr size_t O_WXP  = O_WKVS + SZWKV;
constexpr size_t O_WSP  = O_WXP + SZWP;
constexpr size_t O_Q1X  = O_WSP + SZWP;
constexpr size_t O_Q1S  = O_Q1X + SZA;
constexpr size_t O_Q2X  = O_Q1S + SZA;
constexpr size_t O_Q2S  = O_Q2X + SZA;
constexpr size_t O_KVXP = O_Q2S + SZA;
constexpr size_t O_KVSP = O_KVXP + SZKV;
constexpr size_t O_XCAT = O_KVSP + SZKV;
constexpr size_t O_SCAT = O_XCAT + SZCAT;
constexpr size_t POOL_TOT = O_SCAT + SZCAT;

__device__ __nv_bfloat16 g_h[POOL_TOT];
__device__ __nv_bfloat16 g_l[POOL_TOT];

// ======================= helpers =======================
__device__ __forceinline__ uint32_t smem_u32(const void* p) {
    uint32_t a;
    asm("{ .reg .u64 t; cvta.to.shared.u64 t, %1; cvt.u32.u64 %0, t; }"
        : "=r"(a) : "l"(p));
    return a;
}
__device__ __forceinline__ uint32_t split_pair(float f0, float f1,
                                               float& r0, float& r1) {
    __nv_bfloat16 h0 = __float2bfloat16_rn(f0);
    __nv_bfloat16 h1 = __float2bfloat16_rn(f1);
    r0 = f0 - __bfloat162float(h0);
    r1 = f1 - __bfloat162float(h1);
    return (uint32_t)__bfloat16_as_ushort(h0) |
           ((uint32_t)__bfloat16_as_ushort(h1) << 16);
}
__device__ __forceinline__ uint32_t pack_pair(float f0, float f1) {
    __nv_bfloat16 h0 = __float2bfloat16_rn(f0);
    __nv_bfloat16 h1 = __float2bfloat16_rn(f1);
    return (uint32_t)__bfloat16_as_ushort(h0) |
           ((uint32_t)__bfloat16_as_ushort(h1) << 16);
}
__device__ __forceinline__ float ex2f(float x) {
    float y;
    asm("ex2.approx.ftz.f32 %0, %1;" : "=f"(y) : "f"(x));
    return y;
}

#define CP16(dst, src) \
    asm volatile("cp.async.cg.shared.global [%0], [%1], 16;" \
                 :: "r"(dst), "l"(src))
#define CP_COMMIT() asm volatile("cp.async.commit_group;" ::: "memory")
#define CP_WAIT(n)  asm volatile("cp.async.wait_group %0;" :: "n"(n) : "memory")

#define LDSM4(r, addr) \
    asm volatile("ldmatrix.sync.aligned.m8n8.x4.shared.b16 {%0,%1,%2,%3}, [%4];" \
                 : "=r"((r)[0]), "=r"((r)[1]), "=r"((r)[2]), "=r"((r)[3]) \
                 : "r"(addr))
#define LDSM4T(r, addr) \
    asm volatile("ldmatrix.sync.aligned.m8n8.x4.trans.shared.b16 {%0,%1,%2,%3}, [%4];" \
                 : "=r"((r)[0]), "=r"((r)[1]), "=r"((r)[2]), "=r"((r)[3]) \
                 : "r"(addr))
#define MMA16816(c, a, b0, b1) \
    asm volatile("mma.sync.aligned.m16n8k16.row.col.f32.bf16.bf16.f32 " \
                 "{%0,%1,%2,%3}, {%4,%5,%6,%7}, {%8,%9}, {%0,%1,%2,%3};" \
                 : "+f"((c)[0]), "+f"((c)[1]), "+f"((c)[2]), "+f"((c)[3]) \
                 : "r"((a)[0]), "r"((a)[1]), "r"((a)[2]), "r"((a)[3]), \
                   "r"(b0), "r"(b1))

// ======================= fused split kernel =======================
struct SplitArgs { const float* s[12]; };

constexpr size_t S4A   = SZA / 4;
constexpr size_t S4W   = SZW / 4;
constexpr size_t S4WKV = SZWKV / 4;
constexpr size_t S4WP  = SZWP / 4;
constexpr size_t SPLIT_N4 = 4 * S4A + 4 * S4W + 2 * S4WKV + 2 * S4WP;

__global__ __launch_bounds__(256) void split_all(SplitArgs args)
{
    const size_t bnd[13] = {
        0,
        S4A, 2 * S4A, 3 * S4A, 4 * S4A,
        4 * S4A + S4W, 4 * S4A + 2 * S4W, 4 * S4A + 3 * S4W, 4 * S4A + 4 * S4W,
        4 * S4A + 4 * S4W + S4WKV, 4 * S4A + 4 * S4W + 2 * S4WKV,
        4 * S4A + 4 * S4W + 2 * S4WKV + S4WP,
        SPLIT_N4
    };
    size_t idx = (size_t)blockIdx.x * 256 + threadIdx.x;
    int s = 0;
    #pragma unroll
    for (int k = 1; k < 12; ++k) s += (idx >= bnd[k]) ? 1 : 0;
    float4 v = ((const float4*)args.s[s])[idx - bnd[s]];
    float r0, r1, r2, r3;
    uint32_t h0 = split_pair(v.x, v.y, r0, r1);
    uint32_t h1 = split_pair(v.z, v.w, r2, r3);
    ((uint2*)g_h)[idx] = make_uint2(h0, h1);
    ((uint2*)g_l)[idx] = make_uint2(pack_pair(r0, r1), pack_pair(r2, r3));
}

// ======================= GEMM core: 128x128, GBK=64, 3-stage, single-sync =======================
#define BM 128
#define BN 128
#define GBK 64
#define ASTR 72     // 64+8 bf16 -> 144B rows
#define BSTR 136    // 128+8 bf16 -> 272B rows
#define A_EL (BM * ASTR)                 // 9216
#define B_EL (GBK * BSTR)                // 8704
#define STG_EL (2 * A_EL + 2 * B_EL)     // 35840
#define GSMEM (3 * STG_EL * 2)           // 215040 bytes

__device__ __forceinline__ void gemm_core(
    const __nv_bfloat16* __restrict__ Ah, const __nv_bfloat16* __restrict__ Al,
    const __nv_bfloat16* __restrict__ Bh, const __nv_bfloat16* __restrict__ Bl,
    const float* __restrict__ bias, float* __restrict__ Cf,
    __nv_bfloat16* __restrict__ Ch, __nv_bfloat16* __restrict__ Cl,
    int N, int K, int m0, int n0, uint16_t* sg)
{
    const uint32_t sb = smem_u32(sg);
    const int tid  = threadIdx.x;
    const int wid  = tid >> 5;
    const int lane = tid & 31;
    const int wm   = wid >> 2;
    const int wn   = wid & 3;

    const int a_r = tid >> 3, a_s = tid & 7;
    const int b_r = tid >> 4, b_s = tid & 15;
    const __nv_bfloat16* Ah0 = Ah + (size_t)(m0 + a_r) * K + a_s * 8;
    const __nv_bfloat16* Al0 = Al + (size_t)(m0 + a_r) * K + a_s * 8;
    const __nv_bfloat16* Bh0 = Bh + (size_t)b_r * N + n0 + b_s * 8;
    const __nv_bfloat16* Bl0 = Bl + (size_t)b_r * N + n0 + b_s * 8;
    const uint32_t a_dst = (uint32_t)a_r * 144 + a_s * 16;
    const uint32_t b_dst = (uint32_t)b_r * 272 + b_s * 16;

    const int NCH = K / GBK;

    #define G_ISSUE(ck) do { \
        const int _st = (ck) % 3; \
        const uint32_t _ab = sb + _st * STG_EL * 2; \
        const uint32_t _bb = _ab + 2 * A_EL * 2; \
        const size_t _ka = (size_t)(ck) * GBK; \
        const size_t _kb = (size_t)(ck) * GBK * N; \
        _Pragma("unroll") \
        for (int j = 0; j < 4; ++j) { \
            CP16(_ab + a_dst + j * 32 * 144,            Ah0 + _ka + (size_t)j * 32 * K); \
            CP16(_ab + A_EL * 2 + a_dst + j * 32 * 144, Al0 + _ka + (size_t)j * 32 * K); \
            CP16(_bb + b_dst + j * 16 * 272,            Bh0 + _kb + (size_t)j * 16 * N); \
            CP16(_bb + B_EL * 2 + b_dst + j * 16 * 272, Bl0 + _kb + (size_t)j * 16 * N); \
        } \
        CP_COMMIT(); \
    } while (0)

    const uint32_t la = lane & 15, lh = lane >> 4;
    const uint32_t aoff = ((uint32_t)(wm * 64 + la) * ASTR) * 2 + lh * 16;
    const uint32_t boff = ((uint32_t)la * BSTR + wn * 32 + lh * 8) * 2;

    float acc[4][4][4] = {};

    G_ISSUE(0);
    G_ISSUE(1);

    for (int c = 0; c < NCH; ++c) {
        if (c + 1 < NCH) CP_WAIT(1); else CP_WAIT(0);
        __syncthreads();
        // issue stage c+2 -> buffer (c+2)%3 == (c-1)%3, whose reads (iter c-1)
        // were ordered by the barrier just passed. Single sync per chunk.
        if (c + 2 < NCH) G_ISSUE(c + 2);

        const int st = c % 3;
        const uint32_t ash = sb + st * STG_EL * 2;
        const uint32_t asl = ash + A_EL * 2;
        const uint32_t bsh = asl + A_EL * 2;
        const uint32_t bsl = bsh + B_EL * 2;

        #pragma unroll
        for (int ks = 0; ks < 4; ++ks) {
            uint32_t ah[4][4], al[4][4];
            #pragma unroll
            for (int mi = 0; mi < 4; ++mi) {
                uint32_t off = aoff + (uint32_t)mi * 16 * ASTR * 2 + ks * 32;
                LDSM4(ah[mi], ash + off);
                LDSM4(al[mi], asl + off);
            }
            uint32_t bh[2][4], bl[2][4];
            #pragma unroll
            for (int nh = 0; nh < 2; ++nh) {
                uint32_t off = boff + (uint32_t)ks * 16 * BSTR * 2 + nh * 32;
                LDSM4T(bh[nh], bsh + off);
                LDSM4T(bl[nh], bsl + off);
            }
            #pragma unroll
            for (int mi = 0; mi < 4; ++mi) {
                #pragma unroll
                for (int nb = 0; nb < 4; ++nb) {
                    uint32_t bh0 = bh[nb >> 1][(nb & 1) * 2];
                    uint32_t bh1 = bh[nb >> 1][(nb & 1) * 2 + 1];
                    uint32_t bl0 = bl[nb >> 1][(nb & 1) * 2];
                    uint32_t bl1 = bl[nb >> 1][(nb & 1) * 2 + 1];
                    MMA16816(acc[mi][nb], ah[mi], bh0, bh1);
                    MMA16816(acc[mi][nb], ah[mi], bl0, bl1);
                    MMA16816(acc[mi][nb], al[mi], bh0, bh1);
                }
            }
        }
    }
    #undef G_ISSUE

    const int lrow = lane >> 2, lcol = (lane & 3) * 2;
    if (Cf) {
        #pragma unroll
        for (int mi = 0; mi < 4; ++mi) {
            const int r0 = m0 + wm * 64 + mi * 16 + lrow;
            #pragma unroll
            for (int nb = 0; nb < 4; ++nb) {
                const int cc = n0 + wn * 32 + nb * 8 + lcol;
                float b0 = bias[cc], b1 = bias[cc + 1];
                *(float2*)(Cf + (size_t)r0 * N + cc) =
                    make_float2(acc[mi][nb][0] + b0, acc[mi][nb][1] + b1);
                *(float2*)(Cf + (size_t)(r0 + 8) * N + cc) =
                    make_float2(acc[mi][nb][2] + b0, acc[mi][nb][3] + b1);
            }
        }
    } else {
        #pragma unroll
        for (int mi = 0; mi < 4; ++mi) {
            const int r0 = m0 + wm * 64 + mi * 16 + lrow;
            #pragma unroll
            for (int nb = 0; nb < 4; ++nb) {
                const int cc = n0 + wn * 32 + nb * 8 + lcol;
                float e0, e1;
                uint32_t hp0 = split_pair(acc[mi][nb][0], acc[mi][nb][1], e0, e1);
                uint32_t lp0 = pack_pair(e0, e1);
                uint32_t hp1 = split_pair(acc[mi][nb][2], acc[mi][nb][3], e0, e1);
                uint32_t lp1 = pack_pair(e0, e1);
                *(uint32_t*)(Ch + (size_t)r0 * N + cc)       = hp0;
                *(uint32_t*)(Cl + (size_t)r0 * N + cc)       = lp0;
                *(uint32_t*)(Ch + (size_t)(r0 + 8) * N + cc) = hp1;
                *(uint32_t*)(Cl + (size_t)(r0 + 8) * N + cc) = lp1;
            }
        }
    }
}

// ---- fused projection GEMM: 6 jobs, flat grid of 1088 tiles ----
struct GJob { size_t a, b, c; int n; };
__device__ const GJob PROJ_JOBS[6] = {
    {O_QX,   O_WQX1, O_Q1X,  1024},
    {O_QS,   O_WQS1, O_Q1S,  1024},
    {O_QX,   O_WQX2, O_Q2X,  1024},
    {O_QS,   O_WQS2, O_Q2S,  1024},
    {O_KVXI, O_WKVX, O_KVXP, 128},
    {O_KVSI, O_WKVS, O_KVSP, 128},
};

__global__ __launch_bounds__(256, 1) void proj_gemm()
{
    extern __shared__ uint16_t sg[];
    const int t = blockIdx.x;
    int job, mblk, nblk;
    if (t < 1024) { job = t >> 8; int r = t & 255; nblk = r & 7; mblk = r >> 3; }
    else          { int u = t - 1024; job = 4 + (u >> 5); mblk = u & 31; nblk = 0; }
    const GJob j = PROJ_JOBS[job];
    gemm_core(g_h + j.a, g_l + j.a, g_h + j.b, g_l + j.b,
              nullptr, nullptr, g_h + j.c, g_l + j.c,
              j.n, D_MODEL, mblk * BM, nblk * BN, sg);
}

// ---- fused output projections: 2 jobs, 512 tiles ----
__global__ __launch_bounds__(256, 1) void oproj_gemm(
    const float* __restrict__ b_xproj, const float* __restrict__ b_sproj,
    float* __restrict__ out)
{
    extern __shared__ uint16_t sg[];
    const int t = blockIdx.x;
    const int job = t >> 8;
    const int r = t & 255, nblk = r & 7, mblk = r >> 3;
    const size_t ao = job ? O_SCAT : O_XCAT;
    const size_t bo = job ? O_WSP  : O_WXP;
    const float* bias = job ? b_sproj : b_xproj;
    float* o = out + (size_t)job * BL * D_MODEL;
    gemm_core(g_h + ao, g_l + ao, g_h + bo, g_l + bo,
              bias, o, nullptr, nullptr,
              D_MODEL, 2 * D_MODEL, mblk * BM, nblk * BN, sg);
}

// ======================= paired flash attention: TQ=64, 128 thr, 2 CTAs/SM =======================
#define TQ 64
#define TK 64
#define FSTR 72
#define QFSZ (TQ * FSTR)         // 4608
#define KFSZ (TK * FSTR)         // 4608
#define QA_H 0
#define QA_L (QFSZ * 2)
#define QB_H (2 * QFSZ * 2)
#define QB_L (3 * QFSZ * 2)
#define KV_B(st) (4 * QFSZ * 2 + (st) * 4 * KFSZ * 2)
#define ATTN_SMEM (4 * QFSZ * 2 + 2 * 4 * KFSZ * 2)   // 110592

// softmax scale in exp2 domain: 0.125 * log2(e)
#define SOFTMAX_SCL 0.18033688011112042f

__device__ __forceinline__ void softmax_upd(
    float s[8][4], float o[8][4], float* mrow, float* lrow)
{
    #pragma unroll
    for (int r = 0; r < 2; ++r) {
        float tm = -1e30f;
        #pragma unroll
        for (int nb = 0; nb < 8; ++nb) {
            s[nb][2*r]   *= SOFTMAX_SCL;
            s[nb][2*r+1] *= SOFTMAX_SCL;
            tm = fmaxf(tm, fmaxf(s[nb][2*r], s[nb][2*r+1]));
        }
        tm = fmaxf(tm, __shfl_xor_sync(0xffffffffu, tm, 1, 4));
        tm = fmaxf(tm, __shfl_xor_sync(0xffffffffu, tm, 2, 4));
        float mnew  = fmaxf(mrow[r], tm);
        float alpha = ex2f(mrow[r] - mnew);
        mrow[r] = mnew;
        float rs = 0.f;
        #pragma unroll
        for (int nb = 0; nb < 8; ++nb) {
            float p0 = ex2f(s[nb][2*r]   - mnew);
            float p1 = ex2f(s[nb][2*r+1] - mnew);
            s[nb][2*r]   = p0;
            s[nb][2*r+1] = p1;
            rs += p0 + p1;
        }
        rs += __shfl_xor_sync(0xffffffffu, rs, 1, 4);
        rs += __shfl_xor_sync(0xffffffffu, rs, 2, 4);
        lrow[r] = lrow[r] * alpha + rs;
        #pragma unroll
        for (int nf = 0; nf < 8; ++nf) {
            o[nf][2*r]   *= alpha;
            o[nf][2*r+1] *= alpha;
        }
    }
}

__global__ __launch_bounds__(128, 2) void attn_pair()
{
    extern __shared__ uint16_t smA[];
    const uint32_t sb = smem_u32(smA);
    const int tid  = threadIdx.x;
    const int wid  = tid >> 5;          // 0..3
    const int lane = tid & 31;
    const int g    = lane >> 2;
    const int t    = lane & 3;
    const int kvg = blockIdx.z & 1;
    const int b   = blockIdx.z >> 1;
    const int h   = blockIdx.y;
    const int l0  = blockIdx.x * TQ;

    const size_t qAo = kvg ? O_Q2X : O_Q1X;
    const size_t qBo = kvg ? O_Q1S : O_Q2S;
    const size_t kvo = kvg ? O_KVSP : O_KVXP;
    const int colA = kvg ? 0 : D_HEAD;
    const int colB = kvg ? D_HEAD : 0;

    const __nv_bfloat16* kvh = g_h + kvo;
    const __nv_bfloat16* kvl = g_l + kvo;

    const size_t qrow0  = (size_t)b * SEQ + l0;
    const size_t kvrow0 = (size_t)b * SEQ;

    // loader mapping: 128 threads, 64 rows x 8 segs; thread -> row tid>>1,
    // segs (tid&1)*4 .. +3
    const int c_r  = tid >> 1;
    const int c_s4 = (tid & 1) * 4;

    // ---- issue both Q tiles ----
    {
        const size_t qbase = (qrow0 + c_r) * D_MODEL + h * 64;
        #pragma unroll
        for (int j = 0; j < 4; ++j) {
            const int seg = c_s4 + j;
            const uint32_t dd = (uint32_t)c_r * 144 + seg * 16;
            const size_t so = qbase + seg * 8;
            CP16(sb + QA_H + dd, g_h + qAo + so);
            CP16(sb + QA_L + dd, g_l + qAo + so);
            CP16(sb + QB_H + dd, g_h + qBo + so);
            CP16(sb + QB_L + dd, g_l + qBo + so);
        }
    }

    #define A_ISSUE_KV(mt) do { \
        const int _st = (mt) & 1; \
        const uint32_t _kb = sb + KV_B(_st); \
        const size_t _rb = (kvrow0 + (size_t)(mt) * TK + c_r) * 128; \
        _Pragma("unroll") \
        for (int j = 0; j < 4; ++j) { \
            const int _seg = c_s4 + j; \
            const uint32_t _do = (uint32_t)c_r * 144 + _seg * 16; \
            const size_t _sk = _rb + _seg * 8; \
            CP16(_kb + _do,                kvh + _sk);        \
            CP16(_kb + KFSZ * 2 + _do,     kvl + _sk);        \
            CP16(_kb + 2 * KFSZ * 2 + _do, kvh + _sk + 64);   \
            CP16(_kb + 3 * KFSZ * 2 + _do, kvl + _sk + 64);   \
        } \
        CP_COMMIT(); \
    } while (0)

    A_ISSUE_KV(0);
    A_ISSUE_KV(1);

    const uint32_t aoff = ((uint32_t)(wid * 16 + (lane & 15)) * FSTR) * 2
                        + (lane >> 4) * 16;
    const uint32_t koff = ((uint32_t)((lane & 7) + ((lane >> 4) << 3)) * FSTR) * 2
                        + ((lane >> 3) & 1) * 16;
    const uint32_t voff = ((uint32_t)(lane & 15) * FSTR) * 2 + (lane >> 4) * 16;

    float oA[8][4] = {}, oB[8][4] = {};
    float mA[2] = {-1e30f, -1e30f}, lA[2] = {0.f, 0.f};
    float mB[2] = {-1e30f, -1e30f}, lB[2] = {0.f, 0.f};

    for (int mt = 0; mt < SEQ / TK; ++mt) {
        if (mt < SEQ / TK - 1) CP_WAIT(1); else CP_WAIT(0);
        __syncthreads();

        const int st = mt & 1;
        const uint32_t kh_b = sb + KV_B(st);
        const uint32_t kl_b = kh_b + KFSZ * 2;
        const uint32_t vh_b = kh_b + 2 * KFSZ * 2;
        const uint32_t vl_b = kh_b + 3 * KFSZ * 2;

        float sA[8][4] = {}, sB[8][4] = {};
        #pragma unroll
        for (int ks = 0; ks < 4; ++ks) {
            uint32_t ahA[4], alA[4], ahB[4], alB[4];
            LDSM4(ahA, sb + QA_H + aoff + ks * 32);
            LDSM4(alA, sb + QA_L + aoff + ks * 32);
            LDSM4(ahB, sb + QB_H + aoff + ks * 32);
            LDSM4(alB, sb + QB_L + aoff + ks * 32);
            #pragma unroll
            for (int ng = 0; ng < 4; ++ng) {
                uint32_t ko = koff + (uint32_t)ng * 16 * FSTR * 2 + ks * 32;
                uint32_t kh[4], kl[4];
                LDSM4(kh, kh_b + ko);
                LDSM4(kl, kl_b + ko);
                MMA16816(sA[2*ng],   ahA, kh[0], kh[1]);
                MMA16816(sA[2*ng],   ahA, kl[0], kl[1]);
                MMA16816(sA[2*ng],   alA, kh[0], kh[1]);
                MMA16816(sA[2*ng+1], ahA, kh[2], kh[3]);
                MMA16816(sA[2*ng+1], ahA, kl[2], kl[3]);
                MMA16816(sA[2*ng+1], alA, kh[2], kh[3]);
                MMA16816(sB[2*ng],   ahB, kh[0], kh[1]);
                MMA16816(sB[2*ng],   ahB, kl[0], kl[1]);
                MMA16816(sB[2*ng],   alB, kh[0], kh[1]);
                MMA16816(sB[2*ng+1], ahB, kh[2], kh[3]);
                MMA16816(sB[2*ng+1], ahB, kl[2], kl[3]);
                MMA16816(sB[2*ng+1], alB, kh[2], kh[3]);
            }
        }

        softmax_upd(sA, oA, mA, lA);
        softmax_upd(sB, oB, mB, lB);

        #pragma unroll
        for (int ks = 0; ks < 4; ++ks) {
            uint32_t pahA[4], palA[4], pahB[4], palB[4];
            {
                float e0, e1;
                pahA[0] = split_pair(sA[2*ks][0],   sA[2*ks][1],   e0, e1); palA[0] = pack_pair(e0, e1);
                pahA[1] = split_pair(sA[2*ks][2],   sA[2*ks][3],   e0, e1); palA[1] = pack_pair(e0, e1);
                pahA[2] = split_pair(sA[2*ks+1][0], sA[2*ks+1][1], e0, e1); palA[2] = pack_pair(e0, e1);
                pahA[3] = split_pair(sA[2*ks+1][2], sA[2*ks+1][3], e0, e1); palA[3] = pack_pair(e0, e1);
                pahB[0] = split_pair(sB[2*ks][0],   sB[2*ks][1],   e0, e1); palB[0] = pack_pair(e0, e1);
                pahB[1] = split_pair(sB[2*ks][2],   sB[2*ks][3],   e0, e1); palB[1] = pack_pair(e0, e1);
                pahB[2] = split_pair(sB[2*ks+1][0], sB[2*ks+1][1], e0, e1); palB[2] = pack_pair(e0, e1);
                pahB[3] = split_pair(sB[2*ks+1][2], sB[2*ks+1][3], e0, e1); palB[3] = pack_pair(e0, e1);
            }
            #pragma unroll
            for (int vg = 0; vg < 4; ++vg) {
                uint32_t vo = voff + (uint32_t)ks * 16 * FSTR * 2 + vg * 32;
                uint32_t vh[4], vl[4];
                LDSM4T(vh, vh_b + vo);
                LDSM4T(vl, vl_b + vo);
                MMA16816(oA[2*vg],   pahA, vh[0], vh[1]);
                MMA16816(oA[2*vg],   pahA, vl[0], vl[1]);
                MMA16816(oA[2*vg],   palA, vh[0], vh[1]);
                MMA16816(oA[2*vg+1], pahA, vh[2], vh[3]);
                MMA16816(oA[2*vg+1], pahA, vl[2], vl[3]);
                MMA16816(oA[2*vg+1], palA, vh[2], vh[3]);
                MMA16816(oB[2*vg],   pahB, vh[0], vh[1]);
                MMA16816(oB[2*vg],   pahB, vl[0], vl[1]);
                MMA16816(oB[2*vg],   palB, vh[0], vh[1]);
                MMA16816(oB[2*vg+1], pahB, vh[2], vh[3]);
                MMA16816(oB[2*vg+1], pahB, vl[2], vl[3]);
                MMA16816(oB[2*vg+1], palB, vh[2], vh[3]);
            }
        }

        __syncthreads();
        if (mt + 2 < SEQ / TK) A_ISSUE_KV(mt + 2);
    }
    #undef A_ISSUE_KV

    #pragma unroll
    for (int r = 0; r < 2; ++r) {
        float invA = 1.0f / lA[r];
        float invB = 1.0f / lB[r];
        const int rr = g + r * 8;
        const size_t rbase = (qrow0 + wid * 16 + rr) * (2 * D_MODEL)
                           + h * (2 * D_HEAD);
        #pragma unroll
        for (int nf = 0; nf < 8; ++nf) {
            const int c = nf * 8 + t * 2;
            float e0, e1;
            float a0 = oA[nf][2*r] * invA, a1 = oA[nf][2*r+1] * invA;
            uint32_t hpA = split_pair(a0, a1, e0, e1);
            uint32_t lpA = pack_pair(e0, e1);
            size_t idxA = rbase + colA + c;
            *(uint32_t*)(g_h + O_XCAT + idxA) = hpA;
            *(uint32_t*)(g_l + O_XCAT + idxA) = lpA;
            float b0 = oB[nf][2*r] * invB, b1 = oB[nf][2*r+1] * invB;
            uint32_t hpB = split_pair(b0, b1, e0, e1);
            uint32_t lpB = pack_pair(e0, e1);
            size_t idxB = rbase + colB + c;
            *(uint32_t*)(g_h + O_SCAT + idxB) = hpB;
            *(uint32_t*)(g_l + O_SCAT + idxB) = lpB;
        }
    }
}

// ---------------- launch ----------------
extern "C" void kernel_launch(void* const* d_in, const int* in_sizes, int n_in,
                              void* d_out, int out_size)
{
    (void)in_sizes; (void)n_in; (void)out_size;
    const float* b_xproj = (const float*)d_in[11];
    const float* b_sproj = (const float*)d_in[13];
    float* out = (float*)d_out;

    cudaFuncSetAttribute(proj_gemm, cudaFuncAttributeMaxDynamicSharedMemorySize,
                         GSMEM);
    cudaFuncSetAttribute(oproj_gemm, cudaFuncAttributeMaxDynamicSharedMemorySize,
                         GSMEM);
    cudaFuncSetAttribute(attn_pair, cudaFuncAttributeMaxDynamicSharedMemorySize,
                         ATTN_SMEM);

    SplitArgs sa;
    sa.s[0]  = (const float*)d_in[0];
    sa.s[1]  = (const float*)d_in[2];
    sa.s[2]  = (const float*)d_in[1];
    sa.s[3]  = (const float*)d_in[3];
    sa.s[4]  = (const float*)d_in[4];
    sa.s[5]  = (const float*)d_in[5];
    sa.s[6]  = (const float*)d_in[6];
    sa.s[7]  = (const float*)d_in[7];
    sa.s[8]  = (const float*)d_in[8];
    sa.s[9]  = (const float*)d_in[9];
    sa.s[10] = (const float*)d_in[10];
    sa.s[11] = (const float*)d_in[12];
    split_all<<<(unsigned)(SPLIT_N4 / 256), 256>>>(sa);

    proj_gemm<<<1088, 256, GSMEM>>>();

    // paired attention: z = b*2 + kv_group; TQ=64 -> grid.x = 16
    attn_pair<<<dim3(SEQ / TQ, N_HEAD, BATCH * 2), 128, ATTN_SMEM>>>();

    oproj_gemm<<<512, 256, GSMEM>>>(b_xproj, b_sproj, out);
}

// round 15
// speedup vs baseline: 1.1038x; 1.1038x over previous
#include <cuda_runtime.h>
#include <cuda_bf16.h>
#include <cstdint>

#define D_MODEL 1024
#define N_HEAD  16
#define D_HEAD  64
#define BATCH   4
#define SEQ     1024
#define BL      (BATCH*SEQ)     // 4096

// ---------------- bf16 hi/lo pools (static device globals) ----------------
constexpr size_t SZA   = (size_t)BL * D_MODEL;
constexpr size_t SZW   = (size_t)D_MODEL * D_MODEL;
constexpr size_t SZWKV = (size_t)D_MODEL * 128;
constexpr size_t SZWP  = (size_t)2 * D_MODEL * D_MODEL;
constexpr size_t SZKV  = (size_t)BL * 128;
constexpr size_t SZCAT = (size_t)BL * 2 * D_MODEL;

constexpr size_t O_QX   = 0;
constexpr size_t O_QS   = O_QX + SZA;
constexpr size_t O_KVXI = O_QS + SZA;
constexpr size_t O_KVSI = O_KVXI + SZA;
constexpr size_t O_WQX1 = O_KVSI + SZA;
constexpr size_t O_WQS1 = O_WQX1 + SZW;
constexpr size_t O_WQX2 = O_WQS1 + SZW;
constexpr size_t O_WQS2 = O_WQX2 + SZW;
constexpr size_t O_WKVX = O_WQS2 + SZW;
constexpr size_t O_WKVS = O_WKVX + SZWKV;
constexpr size_t O_WXP  = O_WKVS + SZWKV;
constexpr size_t O_WSP  = O_WXP + SZWP;
constexpr size_t O_Q1X  = O_WSP + SZWP;
constexpr size_t O_Q1S  = O_Q1X + SZA;
constexpr size_t O_Q2X  = O_Q1S + SZA;
constexpr size_t O_Q2S  = O_Q2X + SZA;
constexpr size_t O_KVXP = O_Q2S + SZA;
constexpr size_t O_KVSP = O_KVXP + SZKV;
constexpr size_t O_XCAT = O_KVSP + SZKV;
constexpr size_t O_SCAT = O_XCAT + SZCAT;
constexpr size_t POOL_TOT = O_SCAT + SZCAT;

__device__ __nv_bfloat16 g_h[POOL_TOT];
__device__ __nv_bfloat16 g_l[POOL_TOT];

// ======================= helpers =======================
__device__ __forceinline__ uint32_t smem_u32(const void* p) {
    uint32_t a;
    asm("{ .reg .u64 t; cvta.to.shared.u64 t, %1; cvt.u32.u64 %0, t; }"
        : "=r"(a) : "l"(p));
    return a;
}
__device__ __forceinline__ uint32_t split_pair(float f0, float f1,
                                               float& r0, float& r1) {
    __nv_bfloat16 h0 = __float2bfloat16_rn(f0);
    __nv_bfloat16 h1 = __float2bfloat16_rn(f1);
    r0 = f0 - __bfloat162float(h0);
    r1 = f1 - __bfloat162float(h1);
    return (uint32_t)__bfloat16_as_ushort(h0) |
           ((uint32_t)__bfloat16_as_ushort(h1) << 16);
}
__device__ __forceinline__ uint32_t pack_pair(float f0, float f1) {
    __nv_bfloat16 h0 = __float2bfloat16_rn(f0);
    __nv_bfloat16 h1 = __float2bfloat16_rn(f1);
    return (uint32_t)__bfloat16_as_ushort(h0) |
           ((uint32_t)__bfloat16_as_ushort(h1) << 16);
}
__device__ __forceinline__ float ex2f(float x) {
    float y;
    asm("ex2.approx.ftz.f32 %0, %1;" : "=f"(y) : "f"(x));
    return y;
}

#define CP16(dst, src) \
    asm volatile("cp.async.cg.shared.global [%0], [%1], 16;" \
                 :: "r"(dst), "l"(src))
#define CP_COMMIT() asm volatile("cp.async.commit_group;" ::: "memory")
#define CP_WAIT(n)  asm volatile("cp.async.wait_group %0;" :: "n"(n) : "memory")

#define LDSM4(r, addr) \
    asm volatile("ldmatrix.sync.aligned.m8n8.x4.shared.b16 {%0,%1,%2,%3}, [%4];" \
                 : "=r"((r)[0]), "=r"((r)[1]), "=r"((r)[2]), "=r"((r)[3]) \
                 : "r"(addr))
#define LDSM4T(r, addr) \
    asm volatile("ldmatrix.sync.aligned.m8n8.x4.trans.shared.b16 {%0,%1,%2,%3}, [%4];" \
                 : "=r"((r)[0]), "=r"((r)[1]), "=r"((r)[2]), "=r"((r)[3]) \
                 : "r"(addr))
#define MMA16816(c, a, b0, b1) \
    asm volatile("mma.sync.aligned.m16n8k16.row.col.f32.bf16.bf16.f32 " \
                 "{%0,%1,%2,%3}, {%4,%5,%6,%7}, {%8,%9}, {%0,%1,%2,%3};" \
                 : "+f"((c)[0]), "+f"((c)[1]), "+f"((c)[2]), "+f"((c)[3]) \
                 : "r"((a)[0]), "r"((a)[1]), "r"((a)[2]), "r"((a)[3]), \
                   "r"(b0), "r"(b1))

// ======================= fused split kernel =======================
struct SplitArgs { const float* s[12]; };

constexpr size_t S4A   = SZA / 4;
constexpr size_t S4W   = SZW / 4;
constexpr size_t S4WKV = SZWKV / 4;
constexpr size_t S4WP  = SZWP / 4;
constexpr size_t SPLIT_N4 = 4 * S4A + 4 * S4W + 2 * S4WKV + 2 * S4WP;

__global__ __launch_bounds__(256) void split_all(SplitArgs args)
{
    const size_t bnd[13] = {
        0,
        S4A, 2 * S4A, 3 * S4A, 4 * S4A,
        4 * S4A + S4W, 4 * S4A + 2 * S4W, 4 * S4A + 3 * S4W, 4 * S4A + 4 * S4W,
        4 * S4A + 4 * S4W + S4WKV, 4 * S4A + 4 * S4W + 2 * S4WKV,
        4 * S4A + 4 * S4W + 2 * S4WKV + S4WP,
        SPLIT_N4
    };
    size_t idx = (size_t)blockIdx.x * 256 + threadIdx.x;
    int s = 0;
    #pragma unroll
    for (int k = 1; k < 12; ++k) s += (idx >= bnd[k]) ? 1 : 0;
    float4 v = ((const float4*)args.s[s])[idx - bnd[s]];
    float r0, r1, r2, r3;
    uint32_t h0 = split_pair(v.x, v.y, r0, r1);
    uint32_t h1 = split_pair(v.z, v.w, r2, r3);
    ((uint2*)g_h)[idx] = make_uint2(h0, h1);
    ((uint2*)g_l)[idx] = make_uint2(pack_pair(r0, r1), pack_pair(r2, r3));
}

// ======================= GEMM core: 256x128 tile, GBK=64, 2-stage =======================
#define BM 256
#define BN 128
#define GBK 64
#define ASTR 72     // 64+8 bf16 -> 144B rows
#define BSTR 136    // 128+8 bf16 -> 272B rows
#define A_EL (BM * ASTR)                 // 18432
#define B_EL (GBK * BSTR)                // 8704
#define STG_EL (2 * A_EL + 2 * B_EL)     // 54272
#define GSMEM (2 * STG_EL * 2)           // 217088 bytes

__device__ __forceinline__ void gemm_core(
    const __nv_bfloat16* __restrict__ Ah, const __nv_bfloat16* __restrict__ Al,
    const __nv_bfloat16* __restrict__ Bh, const __nv_bfloat16* __restrict__ Bl,
    const float* __restrict__ bias, float* __restrict__ Cf,
    __nv_bfloat16* __restrict__ Ch, __nv_bfloat16* __restrict__ Cl,
    int N, int K, int m0, int n0, uint16_t* sg)
{
    const uint32_t sb = smem_u32(sg);
    const int tid  = threadIdx.x;
    const int wid  = tid >> 5;
    const int lane = tid & 31;
    const int wm   = wid >> 1;      // 0..3, 64-row band
    const int wn   = wid & 1;       // 0..1, 64-col band

    const int a_r = tid >> 3, a_s = tid & 7;
    const int b_r = tid >> 4, b_s = tid & 15;
    const __nv_bfloat16* Ah0 = Ah + (size_t)(m0 + a_r) * K + a_s * 8;
    const __nv_bfloat16* Al0 = Al + (size_t)(m0 + a_r) * K + a_s * 8;
    const __nv_bfloat16* Bh0 = Bh + (size_t)b_r * N + n0 + b_s * 8;
    const __nv_bfloat16* Bl0 = Bl + (size_t)b_r * N + n0 + b_s * 8;
    const uint32_t a_dst = (uint32_t)a_r * 144 + a_s * 16;
    const uint32_t b_dst = (uint32_t)b_r * 272 + b_s * 16;

    const int NCH = K / GBK;

    #define G_ISSUE(ck) do { \
        const int _st = (ck) & 1; \
        const uint32_t _ab = sb + _st * STG_EL * 2; \
        const uint32_t _bb = _ab + 2 * A_EL * 2; \
        const size_t _ka = (size_t)(ck) * GBK; \
        const size_t _kb = (size_t)(ck) * GBK * N; \
        _Pragma("unroll") \
        for (int j = 0; j < 8; ++j) { \
            CP16(_ab + a_dst + j * 32 * 144,            Ah0 + _ka + (size_t)j * 32 * K); \
            CP16(_ab + A_EL * 2 + a_dst + j * 32 * 144, Al0 + _ka + (size_t)j * 32 * K); \
        } \
        _Pragma("unroll") \
        for (int j = 0; j < 4; ++j) { \
            CP16(_bb + b_dst + j * 16 * 272,            Bh0 + _kb + (size_t)j * 16 * N); \
            CP16(_bb + B_EL * 2 + b_dst + j * 16 * 272, Bl0 + _kb + (size_t)j * 16 * N); \
        } \
        CP_COMMIT(); \
    } while (0)

    const uint32_t la = lane & 15, lh = lane >> 4;
    const uint32_t aoff = ((uint32_t)(wm * 64 + la) * ASTR) * 2 + lh * 16;
    const uint32_t boff = ((uint32_t)la * BSTR + wn * 64 + lh * 8) * 2;

    float acc[4][8][4] = {};

    G_ISSUE(0);
    G_ISSUE(1);

    for (int c = 0; c < NCH; ++c) {
        if (c + 1 < NCH) CP_WAIT(1); else CP_WAIT(0);
        __syncthreads();

        const int st = c & 1;
        const uint32_t ash = sb + st * STG_EL * 2;
        const uint32_t asl = ash + A_EL * 2;
        const uint32_t bsh = asl + A_EL * 2;
        const uint32_t bsl = bsh + B_EL * 2;

        #pragma unroll
        for (int ks = 0; ks < 4; ++ks) {
            uint32_t ah[4][4], al[4][4];
            #pragma unroll
            for (int mi = 0; mi < 4; ++mi) {
                uint32_t off = aoff + (uint32_t)mi * 16 * ASTR * 2 + ks * 32;
                LDSM4(ah[mi], ash + off);
                LDSM4(al[mi], asl + off);
            }
            #pragma unroll
            for (int nh = 0; nh < 4; ++nh) {
                uint32_t off = boff + (uint32_t)ks * 16 * BSTR * 2 + nh * 32;
                uint32_t bh[4], bl[4];
                LDSM4T(bh, bsh + off);
                LDSM4T(bl, bsl + off);
                #pragma unroll
                for (int mi = 0; mi < 4; ++mi) {
                    #pragma unroll
                    for (int half = 0; half < 2; ++half) {
                        const int nb = nh * 2 + half;
                        uint32_t b0 = bh[half * 2], b1 = bh[half * 2 + 1];
                        uint32_t c0 = bl[half * 2], c1 = bl[half * 2 + 1];
                        MMA16816(acc[mi][nb], ah[mi], b0, b1);
                        MMA16816(acc[mi][nb], ah[mi], c0, c1);
                        MMA16816(acc[mi][nb], al[mi], b0, b1);
                    }
                }
            }
        }
        __syncthreads();
        if (c + 2 < NCH) G_ISSUE(c + 2);
    }
    #undef G_ISSUE

    const int lrow = lane >> 2, lcol = (lane & 3) * 2;
    if (Cf) {
        #pragma unroll
        for (int mi = 0; mi < 4; ++mi) {
            const int r0 = m0 + wm * 64 + mi * 16 + lrow;
            #pragma unroll
            for (int nb = 0; nb < 8; ++nb) {
                const int cc = n0 + wn * 64 + nb * 8 + lcol;
                float b0 = bias[cc], b1 = bias[cc + 1];
                *(float2*)(Cf + (size_t)r0 * N + cc) =
                    make_float2(acc[mi][nb][0] + b0, acc[mi][nb][1] + b1);
                *(float2*)(Cf + (size_t)(r0 + 8) * N + cc) =
                    make_float2(acc[mi][nb][2] + b0, acc[mi][nb][3] + b1);
            }
        }
    } else {
        #pragma unroll
        for (int mi = 0; mi < 4; ++mi) {
            const int r0 = m0 + wm * 64 + mi * 16 + lrow;
            #pragma unroll
            for (int nb = 0; nb < 8; ++nb) {
                const int cc = n0 + wn * 64 + nb * 8 + lcol;
                float e0, e1;
                uint32_t hp0 = split_pair(acc[mi][nb][0], acc[mi][nb][1], e0, e1);
                uint32_t lp0 = pack_pair(e0, e1);
                uint32_t hp1 = split_pair(acc[mi][nb][2], acc[mi][nb][3], e0, e1);
                uint32_t lp1 = pack_pair(e0, e1);
                *(uint32_t*)(Ch + (size_t)r0 * N + cc)       = hp0;
                *(uint32_t*)(Cl + (size_t)r0 * N + cc)       = lp0;
                *(uint32_t*)(Ch + (size_t)(r0 + 8) * N + cc) = hp1;
                *(uint32_t*)(Cl + (size_t)(r0 + 8) * N + cc) = lp1;
            }
        }
    }
}

// ---- fused projection GEMM: 6 jobs, flat grid of 544 tiles ----
struct GJob { size_t a, b, c; int n; };
__device__ const GJob PROJ_JOBS[6] = {
    {O_QX,   O_WQX1, O_Q1X,  1024},
    {O_QS,   O_WQS1, O_Q1S,  1024},
    {O_QX,   O_WQX2, O_Q2X,  1024},
    {O_QS,   O_WQS2, O_Q2S,  1024},
    {O_KVXI, O_WKVX, O_KVXP, 128},
    {O_KVSI, O_WKVS, O_KVSP, 128},
};

__global__ __launch_bounds__(256, 1) void proj_gemm()
{
    extern __shared__ uint16_t sg[];
    const int t = blockIdx.x;
    int job, mblk, nblk;
    if (t < 512) { job = t >> 7; int r = t & 127; nblk = r & 7; mblk = r >> 3; }
    else         { int u = t - 512; job = 4 + (u >> 4); mblk = u & 15; nblk = 0; }
    const GJob j = PROJ_JOBS[job];
    gemm_core(g_h + j.a, g_l + j.a, g_h + j.b, g_l + j.b,
              nullptr, nullptr, g_h + j.c, g_l + j.c,
              j.n, D_MODEL, mblk * BM, nblk * BN, sg);
}

// ---- fused output projections: 2 jobs, 256 tiles ----
__global__ __launch_bounds__(256, 1) void oproj_gemm(
    const float* __restrict__ b_xproj, const float* __restrict__ b_sproj,
    float* __restrict__ out)
{
    extern __shared__ uint16_t sg[];
    const int t = blockIdx.x;
    const int job = t >> 7;
    const int r = t & 127, nblk = r & 7, mblk = r >> 3;
    const size_t ao = job ? O_SCAT : O_XCAT;
    const size_t bo = job ? O_WSP  : O_WXP;
    const float* bias = job ? b_sproj : b_xproj;
    float* o = out + (size_t)job * BL * D_MODEL;
    gemm_core(g_h + ao, g_l + ao, g_h + bo, g_l + bo,
              bias, o, nullptr, nullptr,
              D_MODEL, 2 * D_MODEL, mblk * BM, nblk * BN, sg);
}

// ======================= paired flash attention (R13 config + exp2) =======================
#define TQ 128
#define TK 64
#define FSTR 72
#define QFSZ (TQ * FSTR)         // 9216
#define KFSZ (TK * FSTR)         // 4608
#define QA_H 0
#define QA_L (QFSZ * 2)
#define QB_H (2 * QFSZ * 2)
#define QB_L (3 * QFSZ * 2)
#define KV_B(st) (4 * QFSZ * 2 + (st) * 4 * KFSZ * 2)
#define ATTN_SMEM (4 * QFSZ * 2 + 2 * 4 * KFSZ * 2)   // 147456

// softmax scale in exp2 domain: 0.125 * log2(e)
#define SOFTMAX_SCL 0.18033688011112042f

__device__ __forceinline__ void softmax_upd(
    float s[8][4], float o[8][4], float* mrow, float* lrow)
{
    #pragma unroll
    for (int r = 0; r < 2; ++r) {
        float tm = -1e30f;
        #pragma unroll
        for (int nb = 0; nb < 8; ++nb) {
            s[nb][2*r]   *= SOFTMAX_SCL;
            s[nb][2*r+1] *= SOFTMAX_SCL;
            tm = fmaxf(tm, fmaxf(s[nb][2*r], s[nb][2*r+1]));
        }
        tm = fmaxf(tm, __shfl_xor_sync(0xffffffffu, tm, 1, 4));
        tm = fmaxf(tm, __shfl_xor_sync(0xffffffffu, tm, 2, 4));
        float mnew  = fmaxf(mrow[r], tm);
        float alpha = ex2f(mrow[r] - mnew);
        mrow[r] = mnew;
        float rs = 0.f;
        #pragma unroll
        for (int nb = 0; nb < 8; ++nb) {
            float p0 = ex2f(s[nb][2*r]   - mnew);
            float p1 = ex2f(s[nb][2*r+1] - mnew);
            s[nb][2*r]   = p0;
            s[nb][2*r+1] = p1;
            rs += p0 + p1;
        }
        rs += __shfl_xor_sync(0xffffffffu, rs, 1, 4);
        rs += __shfl_xor_sync(0xffffffffu, rs, 2, 4);
        lrow[r] = lrow[r] * alpha + rs;
        #pragma unroll
        for (int nf = 0; nf < 8; ++nf) {
            o[nf][2*r]   *= alpha;
            o[nf][2*r+1] *= alpha;
        }
    }
}

__global__ __launch_bounds__(256, 1) void attn_pair()
{
    extern __shared__ uint16_t smA[];
    const uint32_t sb = smem_u32(smA);
    const int tid  = threadIdx.x;
    const int wid  = tid >> 5;
    const int lane = tid & 31;
    const int g    = lane >> 2;
    const int t    = lane & 3;
    const int kvg = blockIdx.z & 1;
    const int b   = blockIdx.z >> 1;
    const int h   = blockIdx.y;
    const int l0  = blockIdx.x * TQ;

    const size_t qAo = kvg ? O_Q2X : O_Q1X;
    const size_t qBo = kvg ? O_Q1S : O_Q2S;
    const size_t kvo = kvg ? O_KVSP : O_KVXP;
    const int colA = kvg ? 0 : D_HEAD;
    const int colB = kvg ? D_HEAD : 0;

    const __nv_bfloat16* kvh = g_h + kvo;
    const __nv_bfloat16* kvl = g_l + kvo;

    const size_t qrow0  = (size_t)b * SEQ + l0;
    const size_t kvrow0 = (size_t)b * SEQ;

    const int c_r = tid >> 3, c_s = tid & 7;
    const uint32_t q_dst = (uint32_t)c_r * 144 + c_s * 16;

    {
        const size_t qoff = (qrow0 + c_r) * D_MODEL + h * 64 + c_s * 8;
        #pragma unroll
        for (int j = 0; j < 4; ++j) {
            const size_t ro = (size_t)j * 32 * D_MODEL;
            const uint32_t dd = q_dst + j * 32 * 144;
            CP16(sb + QA_H + dd, g_h + qAo + qoff + ro);
            CP16(sb + QA_L + dd, g_l + qAo + qoff + ro);
            CP16(sb + QB_H + dd, g_h + qBo + qoff + ro);
            CP16(sb + QB_L + dd, g_l + qBo + qoff + ro);
        }
    }

    #define A_ISSUE_KV(mt) do { \
        const int _st = (mt) & 1; \
        const uint32_t _kb = sb + KV_B(_st); \
        const __nv_bfloat16* _kh = kvh + (kvrow0 + (size_t)(mt) * TK + c_r) * 128 + c_s * 8; \
        const __nv_bfloat16* _kl = kvl + (kvrow0 + (size_t)(mt) * TK + c_r) * 128 + c_s * 8; \
        _Pragma("unroll") \
        for (int j = 0; j < 2; ++j) { \
            const size_t _ro = (size_t)j * 32 * 128; \
            const uint32_t _do = q_dst + j * 32 * 144; \
            CP16(_kb + _do,                 _kh + _ro);        \
            CP16(_kb + KFSZ * 2 + _do,      _kl + _ro);        \
            CP16(_kb + 2 * KFSZ * 2 + _do,  _kh + _ro + 64);   \
            CP16(_kb + 3 * KFSZ * 2 + _do,  _kl + _ro + 64);   \
        } \
        CP_COMMIT(); \
    } while (0)

    A_ISSUE_KV(0);
    A_ISSUE_KV(1);

    const uint32_t aoff = ((uint32_t)(wid * 16 + (lane & 15)) * FSTR) * 2
                        + (lane >> 4) * 16;
    const uint32_t koff = ((uint32_t)((lane & 7) + ((lane >> 4) << 3)) * FSTR) * 2
                        + ((lane >> 3) & 1) * 16;
    const uint32_t voff = ((uint32_t)(lane & 15) * FSTR) * 2 + (lane >> 4) * 16;

    float oA[8][4] = {}, oB[8][4] = {};
    float mA[2] = {-1e30f, -1e30f}, lA[2] = {0.f, 0.f};
    float mB[2] = {-1e30f, -1e30f}, lB[2] = {0.f, 0.f};

    for (int mt = 0; mt < SEQ / TK; ++mt) {
        if (mt < SEQ / TK - 1) CP_WAIT(1); else CP_WAIT(0);
        __syncthreads();

        const int st = mt & 1;
        const uint32_t kh_b = sb + KV_B(st);
        const uint32_t kl_b = kh_b + KFSZ * 2;
        const uint32_t vh_b = kh_b + 2 * KFSZ * 2;
        const uint32_t vl_b = kh_b + 3 * KFSZ * 2;

        float sA[8][4] = {}, sB[8][4] = {};
        #pragma unroll
        for (int ks = 0; ks < 4; ++ks) {
            uint32_t ahA[4], alA[4], ahB[4], alB[4];
            LDSM4(ahA, sb + QA_H + aoff + ks * 32);
            LDSM4(alA, sb + QA_L + aoff + ks * 32);
            LDSM4(ahB, sb + QB_H + aoff + ks * 32);
            LDSM4(alB, sb + QB_L + aoff + ks * 32);
            #pragma unroll
            for (int ng = 0; ng < 4; ++ng) {
                uint32_t ko = koff + (uint32_t)ng * 16 * FSTR * 2 + ks * 32;
                uint32_t kh[4], kl[4];
                LDSM4(kh, kh_b + ko);
                LDSM4(kl, kl_b + ko);
                MMA16816(sA[2*ng],   ahA, kh[0], kh[1]);
                MMA16816(sA[2*ng],   ahA, kl[0], kl[1]);
                MMA16816(sA[2*ng],   alA, kh[0], kh[1]);
                MMA16816(sA[2*ng+1], ahA, kh[2], kh[3]);
                MMA16816(sA[2*ng+1], ahA, kl[2], kl[3]);
                MMA16816(sA[2*ng+1], alA, kh[2], kh[3]);
                MMA16816(sB[2*ng],   ahB, kh[0], kh[1]);
                MMA16816(sB[2*ng],   ahB, kl[0], kl[1]);
                MMA16816(sB[2*ng],   alB, kh[0], kh[1]);
                MMA16816(sB[2*ng+1], ahB, kh[2], kh[3]);
                MMA16816(sB[2*ng+1], ahB, kl[2], kl[3]);
                MMA16816(sB[2*ng+1], alB, kh[2], kh[3]);
            }
        }

        softmax_upd(sA, oA, mA, lA);
        softmax_upd(sB, oB, mB, lB);

        #pragma unroll
        for (int ks = 0; ks < 4; ++ks) {
            uint32_t pahA[4], palA[4], pahB[4], palB[4];
            {
                float e0, e1;
                pahA[0] = split_pair(sA[2*ks][0],   sA[2*ks][1],   e0, e1); palA[0] = pack_pair(e0, e1);
                pahA[1] = split_pair(sA[2*ks][2],   sA[2*ks][3],   e0, e1); palA[1] = pack_pair(e0, e1);
                pahA[2] = split_pair(sA[2*ks+1][0], sA[2*ks+1][1], e0, e1); palA[2] = pack_pair(e0, e1);
                pahA[3] = split_pair(sA[2*ks+1][2], sA[2*ks+1][3], e0, e1); palA[3] = pack_pair(e0, e1);
                pahB[0] = split_pair(sB[2*ks][0],   sB[2*ks][1],   e0, e1); palB[0] = pack_pair(e0, e1);
                pahB[1] = split_pair(sB[2*ks][2],   sB[2*ks][3],   e0, e1); palB[1] = pack_pair(e0, e1);
                pahB[2] = split_pair(sB[2*ks+1][0], sB[2*ks+1][1], e0, e1); palB[2] = pack_pair(e0, e1);
                pahB[3] = split_pair(sB[2*ks+1][2], sB[2*ks+1][3], e0, e1); palB[3] = pack_pair(e0, e1);
            }
            #pragma unroll
            for (int vg = 0; vg < 4; ++vg) {
                uint32_t vo = voff + (uint32_t)ks * 16 * FSTR * 2 + vg * 32;
                uint32_t vh[4], vl[4];
                LDSM4T(vh, vh_b + vo);
                LDSM4T(vl, vl_b + vo);
                MMA16816(oA[2*vg],   pahA, vh[0], vh[1]);
                MMA16816(oA[2*vg],   pahA, vl[0], vl[1]);
                MMA16816(oA[2*vg],   palA, vh[0], vh[1]);
                MMA16816(oA[2*vg+1], pahA, vh[2], vh[3]);
                MMA16816(oA[2*vg+1], pahA, vl[2], vl[3]);
                MMA16816(oA[2*vg+1], palA, vh[2], vh[3]);
                MMA16816(oB[2*vg],   pahB, vh[0], vh[1]);
                MMA16816(oB[2*vg],   pahB, vl[0], vl[1]);
                MMA16816(oB[2*vg],   palB, vh[0], vh[1]);
                MMA16816(oB[2*vg+1], pahB, vh[2], vh[3]);
                MMA16816(oB[2*vg+1], pahB, vl[2], vl[3]);
                MMA16816(oB[2*vg+1], palB, vh[2], vh[3]);
            }
        }

        __syncthreads();
        if (mt + 2 < SEQ / TK) A_ISSUE_KV(mt + 2);
    }
    #undef A_ISSUE_KV

    #pragma unroll
    for (int r = 0; r < 2; ++r) {
        float invA = 1.0f / lA[r];
        float invB = 1.0f / lB[r];
        const int rr = g + r * 8;
        const size_t rbase = (qrow0 + wid * 16 + rr) * (2 * D_MODEL)
                           + h * (2 * D_HEAD);
        #pragma unroll
        for (int nf = 0; nf < 8; ++nf) {
            const int c = nf * 8 + t * 2;
            float e0, e1;
            float a0 = oA[nf][2*r] * invA, a1 = oA[nf][2*r+1] * invA;
            uint32_t hpA = split_pair(a0, a1, e0, e1);
            uint32_t lpA = pack_pair(e0, e1);
            size_t idxA = rbase + colA + c;
            *(uint32_t*)(g_h + O_XCAT + idxA) = hpA;
            *(uint32_t*)(g_l + O_XCAT + idxA) = lpA;
            float b0 = oB[nf][2*r] * invB, b1 = oB[nf][2*r+1] * invB;
            uint32_t hpB = split_pair(b0, b1, e0, e1);
            uint32_t lpB = pack_pair(e0, e1);
            size_t idxB = rbase + colB + c;
            *(uint32_t*)(g_h + O_SCAT + idxB) = hpB;
            *(uint32_t*)(g_l + O_SCAT + idxB) = lpB;
        }
    }
}

// ---------------- launch ----------------
extern "C" void kernel_launch(void* const* d_in, const int* in_sizes, int n_in,
                              void* d_out, int out_size)
{
    (void)in_sizes; (void)n_in; (void)out_size;
    const float* b_xproj = (const float*)d_in[11];
    const float* b_sproj = (const float*)d_in[13];
    float* out = (float*)d_out;

    cudaFuncSetAttribute(proj_gemm, cudaFuncAttributeMaxDynamicSharedMemorySize,
                         GSMEM);
    cudaFuncSetAttribute(oproj_gemm, cudaFuncAttributeMaxDynamicSharedMemorySize,
                         GSMEM);
    cudaFuncSetAttribute(attn_pair, cudaFuncAttributeMaxDynamicSharedMemorySize,
                         ATTN_SMEM);

    SplitArgs sa;
    sa.s[0]  = (const float*)d_in[0];
    sa.s[1]  = (const float*)d_in[2];
    sa.s[2]  = (const float*)d_in[1];
    sa.s[3]  = (const float*)d_in[3];
    sa.s[4]  = (const float*)d_in[4];
    sa.s[5]  = (const float*)d_in[5];
    sa.s[6]  = (const float*)d_in[6];
    sa.s[7]  = (const float*)d_in[7];
    sa.s[8]  = (const float*)d_in[8];
    sa.s[9]  = (const float*)d_in[9];
    sa.s[10] = (const float*)d_in[10];
    sa.s[11] = (const float*)d_in[12];
    split_all<<<(unsigned)(SPLIT_N4 / 256), 256>>>(sa);

    proj_gemm<<<544, 256, GSMEM>>>();

    // paired attention: z = b*2 + kv_group
    attn_pair<<<dim3(SEQ / TQ, N_HEAD, BATCH * 2), 256, ATTN_SMEM>>>();

    oproj_gemm<<<256, 256, GSMEM>>>(b_xproj, b_sproj, out);
}